// round 6
// baseline (speedup 1.0000x reference)
#include <cuda_runtime.h>
#include <cstdint>

// Problem constants
#define B_ 32
#define T_ 32
#define S_ 100
#define H_ 512
#define E_ 300
#define V_ 45000
#define NOOV_ 10
#define VEXT_ 45010
#define NEG_INF_F (-1e12f)

// ---------------- scratch (device globals; no allocation allowed) ----------------
__device__ float g_cat[3200 * 1024];     // concat(tree_output, encoder_outputs)  13.1 MB
__device__ float g_mem[3200 * 512];      // memories [B,S,H]                       6.6 MB
__device__ float g_Wg[812 * 2048];       // stacked [W_ih; W_hh]                   6.7 MB
__device__ float g_bg[2048];             // b_ih + b_hh
__device__ float g_Aemb[1024 * 300];     // gathered embeddings per (t,b)
__device__ float g_Xemb[1024 * 300];     // X_emb = Aemb @ W_red[0:300] + b_red
__device__ float g_xh[2][32 * 812];      // per-step [x(300) | h(512)] double-buffered
__device__ float g_c[2][32 * 512];       // cell state double-buffered
__device__ float g_hc[32 * 1024];        // [h_new(512) | ctx_new(512)]
__device__ float g_gates[32 * 2048];     // LSTM pre-activations
__device__ float g_Z[1024 * 512];        // z for all steps (rows m = t*32+b)
__device__ float g_Energy[1024 * 100];   // masked energies per (t,b,s)

__device__ __forceinline__ float sigf(float x) { return 1.0f / (1.0f + expf(-x)); }

// ---------------- prep kernels ----------------
__global__ void prep_cat_kernel(const float* __restrict__ tree,
                                const float* __restrict__ enc) {
    int idx = blockIdx.x * blockDim.x + threadIdx.x;
    if (idx >= 3200 * 1024) return;
    int m = idx >> 10, k = idx & 1023;
    g_cat[idx] = (k < 512) ? tree[m * 512 + k] : enc[m * 512 + (k - 512)];
}

__global__ void prep_wg_kernel(const float* __restrict__ W_ih, const float* __restrict__ W_hh,
                               const float* __restrict__ b_ih, const float* __restrict__ b_hh) {
    int idx = blockIdx.x * blockDim.x + threadIdx.x;
    if (idx < 2048) g_bg[idx] = b_ih[idx] + b_hh[idx];
    if (idx >= 812 * 2048) return;
    int r = idx >> 11, c = idx & 2047;
    g_Wg[idx] = (r < 300) ? W_ih[r * 2048 + c] : W_hh[(r - 300) * 2048 + c];
}

__global__ void prep_aemb_kernel(const int* __restrict__ trg,
                                 const float* __restrict__ embedding) {
    int idx = blockIdx.x * blockDim.x + threadIdx.x;
    if (idx >= 1024 * 300) return;
    int m = idx / 300, n = idx - m * 300;
    int t = m >> 5, b = m & 31;
    int tok = trg[b * T_ + t];          // trg_seq is [B,T] row-major; scan uses trg.T
    g_Aemb[idx] = embedding[(long)tok * E_ + n];
}

__global__ void init_state_kernel(const float* __restrict__ h0,
                                  const float* __restrict__ c0) {
    int idx = blockIdx.x * blockDim.x + threadIdx.x;
    if (idx < 32 * 812) {
        int b = idx / 812, k = idx - b * 812;
        g_xh[0][idx] = (k < 300) ? g_Xemb[b * 300 + k]          // x0 = X_emb[t=0] (b_red folded in)
                                 : h0[b * 512 + (k - 300)];
    }
    if (idx < 32 * 512) g_c[0][idx] = c0[idx];
}

// ---------------- generic tiled GEMM: C[M,N] = A[M,K] @ B[K,N] + bias ----------------
// 64x64 tile, BK=16, 256 threads, 4x4 microtile.  REMAP: row m = t*32+b -> out row b*32+t.
template <bool REMAP>
__global__ void __launch_bounds__(256)
gemm64_kernel(const float* __restrict__ A, const float* __restrict__ B, int ldb,
              const float* __restrict__ bias, float* __restrict__ C, int ldc,
              int M, int N, int K) {
    __shared__ float As[16][68];
    __shared__ float Bs[16][68];
    int tid = threadIdx.x;
    int tx = tid & 15, ty = tid >> 4;
    int row0 = blockIdx.y * 64, col0 = blockIdx.x * 64;
    float acc[4][4];
#pragma unroll
    for (int i = 0; i < 4; i++)
#pragma unroll
        for (int j = 0; j < 4; j++) acc[i][j] = 0.0f;

    for (int k0 = 0; k0 < K; k0 += 16) {
#pragma unroll
        for (int i = 0; i < 4; i++) {
            int idx = tid + i * 256;           // 0..1023
            int m = idx >> 4, kk = idx & 15;
            int gm = row0 + m, gk = k0 + kk;
            float v = (gm < M && gk < K) ? A[(long)gm * K + gk] : 0.0f;
            As[kk][m] = v;
        }
#pragma unroll
        for (int i = 0; i < 4; i++) {
            int idx = tid + i * 256;
            int kk = idx >> 6, n = idx & 63;
            int gk = k0 + kk, gn = col0 + n;
            float v = (gk < K && gn < N) ? B[(long)gk * ldb + gn] : 0.0f;
            Bs[kk][n] = v;
        }
        __syncthreads();
#pragma unroll
        for (int kk = 0; kk < 16; kk++) {
            float4 a4 = *(const float4*)&As[kk][ty * 4];
            float4 b4 = *(const float4*)&Bs[kk][tx * 4];
            float av[4] = {a4.x, a4.y, a4.z, a4.w};
            float bv[4] = {b4.x, b4.y, b4.z, b4.w};
#pragma unroll
            for (int i = 0; i < 4; i++)
#pragma unroll
                for (int j = 0; j < 4; j++) acc[i][j] += av[i] * bv[j];
        }
        __syncthreads();
    }
#pragma unroll
    for (int i = 0; i < 4; i++) {
        int m = row0 + ty * 4 + i;
        if (m >= M) continue;
        int orow = REMAP ? ((m & 31) * 32 + (m >> 5)) : m;
#pragma unroll
        for (int j = 0; j < 4; j++) {
            int n = col0 + tx * 4 + j;
            if (n >= N) continue;
            float r = acc[i][j] + (bias ? bias[n] : 0.0f);
            C[(long)orow * ldc + n] = r;
        }
    }
}

// ---------------- small GEMM: 32 rows, per-block 16 cols ----------------
// C[32,N] = A[32,K] @ B[K,N] (+bias) (+addm) (opt tanh)
__global__ void __launch_bounds__(256)
small_gemm_kernel(const float* __restrict__ A, int lda, int K,
                  const float* __restrict__ B, int ldb,
                  const float* __restrict__ bias,
                  const float* __restrict__ addm, int ldadd,
                  float* __restrict__ C, int ldc, int N, int act) {
    __shared__ float As[32][33];
    int tid = threadIdx.x;
    int tx = tid & 15, ty = tid >> 4;     // ty: 0..15 -> rows ty and ty+16
    int n = blockIdx.x * 16 + tx;
    float acc0 = 0.0f, acc1 = 0.0f;
    for (int k0 = 0; k0 < K; k0 += 32) {
#pragma unroll
        for (int i = 0; i < 4; i++) {
            int idx = tid + i * 256;
            int m = idx >> 5, kk = idx & 31;
            As[m][kk] = (k0 + kk < K) ? A[m * lda + k0 + kk] : 0.0f;
        }
        __syncthreads();
        if (n < N) {
#pragma unroll 8
            for (int kk = 0; kk < 32; kk++) {
                int gk = k0 + kk;
                float bv = (gk < K) ? B[(long)gk * ldb + n] : 0.0f;
                acc0 += As[ty][kk] * bv;
                acc1 += As[ty + 16][kk] * bv;
            }
        }
        __syncthreads();
    }
    if (n < N) {
        float base = bias ? bias[n] : 0.0f;
        float r0 = acc0 + base + (addm ? addm[ty * ldadd + n] : 0.0f);
        float r1 = acc1 + base + (addm ? addm[(ty + 16) * ldadd + n] : 0.0f);
        if (act) { r0 = tanhf(r0); r1 = tanhf(r1); }
        C[ty * ldc + n] = r0;
        C[(ty + 16) * ldc + n] = r1;
    }
}

// ---------------- fused LSTM nonlinearity + attention (one block per batch row) ----------------
__global__ void __launch_bounds__(256)
lstm_attn_kernel(int t, int p, const unsigned char* __restrict__ mask) {
    int b = blockIdx.x, tid = threadIdx.x;
    __shared__ float h_s[512];
    __shared__ float e_s[100];
    __shared__ float a_s[100];
    __shared__ float sred;

    const float* g = g_gates + b * 2048;
    const float* cp = g_c[p] + b * 512;
    float* cn = g_c[1 - p] + b * 512;
    for (int j = tid; j < 512; j += 256) {
        float gi = g[j], gf = g[512 + j], gg = g[1024 + j], go = g[1536 + j];
        float c = sigf(gf) * cp[j] + sigf(gi) * tanhf(gg);
        float h = sigf(go) * tanhf(c);
        cn[j] = c;
        h_s[j] = h;
        g_xh[1 - p][b * 812 + 300 + j] = h;   // h part of next step's GEMM input
        g_hc[b * 1024 + j] = h;               // for z-GEMM this step
    }
    __syncthreads();

    // energy[s] = h_new . memories[b,s,:]  (masked)
    int w = tid >> 5, lane = tid & 31;
    for (int s = w; s < 100; s += 8) {
        const float* mrow = g_mem + ((long)(b * S_ + s)) * 512;
        float acc = 0.0f;
#pragma unroll 4
        for (int j = lane; j < 512; j += 32) acc += h_s[j] * mrow[j];
#pragma unroll
        for (int o = 16; o; o >>= 1) acc += __shfl_xor_sync(0xffffffffu, acc, o);
        if (lane == 0) {
            float e = mask[b * S_ + s] ? NEG_INF_F : acc;
            e_s[s] = e;
            g_Energy[(t * 32 + b) * 100 + s] = e;
        }
    }
    __syncthreads();

    // softmax over 100 (warp 0)
    if (tid < 32) {
        float m = -3e38f;
        for (int s = lane; s < 100; s += 32) m = fmaxf(m, e_s[s]);
#pragma unroll
        for (int o = 16; o; o >>= 1) m = fmaxf(m, __shfl_xor_sync(0xffffffffu, m, o));
        float sum = 0.0f;
        for (int s = lane; s < 100; s += 32) {
            float v = expf(e_s[s] - m);
            a_s[s] = v;
            sum += v;
        }
#pragma unroll
        for (int o = 16; o; o >>= 1) sum += __shfl_xor_sync(0xffffffffu, sum, o);
        if (lane == 0) sred = sum;
    }
    __syncthreads();

    // ctx_new[j] = sum_s attn[s]*memories[b,s,j]
    float inv = 1.0f / sred;
    for (int j = tid; j < 512; j += 256) {
        float acc = 0.0f;
#pragma unroll 5
        for (int s = 0; s < 100; s++) acc += a_s[s] * g_mem[((long)(b * S_ + s)) * 512 + j];
        g_hc[b * 1024 + 512 + j] = acc * inv;
    }
}

// ---------------- output assembly ----------------
__global__ void oov_fill_kernel(float* __restrict__ out) {
    int idx = blockIdx.x * blockDim.x + threadIdx.x;   // 1024*10
    if (idx >= 1024 * NOOV_) return;
    int row = idx / NOOV_, v = V_ + (idx - row * NOOV_);
    out[(long)row * VEXT_ + v] = NEG_INF_F;   // ext=0, scat->0, out==0 -> -INF (default)
}

__global__ void scatter_kernel(const int* __restrict__ ext_src, float* __restrict__ out) {
    int bt = blockIdx.x;            // row index = b*32 + t
    int b = bt >> 5, t = bt & 31;
    __shared__ int pos_s[100];
    __shared__ float en_s[100];
    int tid = threadIdx.x;
    if (tid < 100) {
        pos_s[tid] = ext_src[b * S_ + tid];
        en_s[tid] = g_Energy[(t * 32 + b) * 100 + tid];
    }
    __syncthreads();
    if (tid < 100) {
        int pos = pos_s[tid];
        bool owner = true;
        float m = en_s[tid];
        for (int s = 0; s < 100; s++) {
            if (s == tid) continue;
            if (pos_s[s] == pos) {
                if (s < tid) owner = false;
                m = fmaxf(m, en_s[s]);
            }
        }
        // scat == -INF means "all contributors masked": reference turns it into 0,
        // leaving out = ext (already in place for pos<V; -INF prefill correct for pos>=V).
        if (owner && m != NEG_INF_F) {
            long off = (long)bt * VEXT_ + pos;
            float base = (pos < V_) ? out[off] : 0.0f;
            float val = base + m;
            if (val == 0.0f) val = NEG_INF_F;
            out[off] = val;
        }
    }
}

// ---------------- launch ----------------
extern "C" void kernel_launch(void* const* d_in, const int* in_sizes, int n_in,
                              void* d_out, int out_size) {
    const int* trg       = (const int*)d_in[0];
    const int* ext_src   = (const int*)d_in[1];
    const float* h0      = (const float*)d_in[2];
    const float* c0      = (const float*)d_in[3];
    const float* tree    = (const float*)d_in[4];
    // d_in[5] = tree_enc_states (unused by the reference)
    const float* enc     = (const float*)d_in[6];
    const unsigned char* mask = (const unsigned char*)d_in[7];
    const float* embedding = (const float*)d_in[8];
    const float* W_enc   = (const float*)d_in[9];
    const float* b_enc   = (const float*)d_in[10];
    const float* W_red   = (const float*)d_in[11];
    const float* b_red   = (const float*)d_in[12];
    const float* W_ih    = (const float*)d_in[13];
    const float* W_hh    = (const float*)d_in[14];
    const float* b_ih    = (const float*)d_in[15];
    const float* b_hh    = (const float*)d_in[16];
    const float* W_cat   = (const float*)d_in[17];
    const float* b_cat   = (const float*)d_in[18];
    const float* W_out   = (const float*)d_in[19];
    const float* b_out   = (const float*)d_in[20];
    float* out = (float*)d_out;

    float *cat_p, *mem_p, *Wg_p, *bg_p, *Aemb_p, *Xemb_p, *xh_p, *hc_p, *gates_p, *Z_p;
    cudaGetSymbolAddress((void**)&cat_p,   g_cat);
    cudaGetSymbolAddress((void**)&mem_p,   g_mem);
    cudaGetSymbolAddress((void**)&Wg_p,    g_Wg);
    cudaGetSymbolAddress((void**)&bg_p,    g_bg);
    cudaGetSymbolAddress((void**)&Aemb_p,  g_Aemb);
    cudaGetSymbolAddress((void**)&Xemb_p,  g_Xemb);
    cudaGetSymbolAddress((void**)&xh_p,    g_xh);
    cudaGetSymbolAddress((void**)&hc_p,    g_hc);
    cudaGetSymbolAddress((void**)&gates_p, g_gates);
    cudaGetSymbolAddress((void**)&Z_p,     g_Z);

    // --- prep (all parallel, independent) ---
    prep_cat_kernel<<<(3200 * 1024 + 255) / 256, 256>>>(tree, enc);
    prep_wg_kernel<<<(812 * 2048 + 255) / 256, 256>>>(W_ih, W_hh, b_ih, b_hh);
    prep_aemb_kernel<<<(1024 * 300 + 255) / 256, 256>>>(trg, embedding);

    // memories = cat @ W_enc + b_enc      [3200,512], K=1024
    gemm64_kernel<false><<<dim3(8, 50), 256>>>(cat_p, W_enc, 512, b_enc, mem_p, 512,
                                               3200, 512, 1024);
    // X_emb = Aemb @ W_red[0:300,:] + b_red   [1024,300], K=300
    gemm64_kernel<false><<<dim3(5, 16), 256>>>(Aemb_p, W_red, 300, b_red, Xemb_p, 300,
                                               1024, 300, 300);
    init_state_kernel<<<(32 * 812 + 255) / 256, 256>>>(h0, c0);

    // --- recurrence: 32 steps, 3-4 small kernels each ---
    for (int t = 0; t < T_; t++) {
        int p = t & 1;
        // gates = [x|h] @ [W_ih;W_hh] + (b_ih+b_hh)   [32,2048], K=812
        small_gemm_kernel<<<128, 256>>>(xh_p + p * 32 * 812, 812, 812,
                                        Wg_p, 2048, bg_p, nullptr, 0,
                                        gates_p, 2048, 2048, 0);
        // LSTM + attention + context (per-batch blocks); stores Energy[t], h/ctx
        lstm_attn_kernel<<<32, 256>>>(t, p, mask);
        // z = tanh([h|ctx] @ W_cat + b_cat) -> Z rows t*32..t*32+31
        small_gemm_kernel<<<32, 256>>>(hc_p, 1024, 1024,
                                       W_cat, 512, b_cat, nullptr, 0,
                                       Z_p + (long)t * 32 * 512, 512, 512, 1);
        // x_{t+1} = X_emb[t+1] + ctx @ W_red[300:812,:]
        if (t + 1 < T_) {
            small_gemm_kernel<<<19, 256>>>(hc_p + 512, 1024, 512,
                                           W_red + 300 * 300, 300, nullptr,
                                           Xemb_p + (long)(t + 1) * 32 * 300, 300,
                                           xh_p + (1 - p) * 32 * 812, 812, 300, 0);
        }
    }

    // --- the hoisted logits GEMM: out[b,t,0:V] = Z @ W_out + b_out  (row remap t*32+b -> b*32+t)
    gemm64_kernel<true><<<dim3((V_ + 63) / 64, 16), 256>>>(Z_p, W_out, V_, b_out,
                                                           out, VEXT_, 1024, V_, 512);
    // --- OOV default (-INF), then pointer scatter-max ---
    oov_fill_kernel<<<(1024 * NOOV_ + 255) / 256, 256>>>(out);
    scatter_kernel<<<1024, 128>>>(ext_src, out);
}